// round 17
// baseline (speedup 1.0000x reference)
#include <cuda_runtime.h>
#include <cuda_bf16.h>
#include <math.h>

#define D_IN   128
#define D_OUT  128
#define KK     64
#define ROWS   4                  // batch rows per block (2 warps per row)

// Scratch (__device__ global per allocation-free rule)
__device__ float g_CD[D_IN * KK * 2 * D_OUT];   // [i][k][{ct,dt}][o]  8MB

// ---------------------------------------------------------------------------
// Prep: fused PCHIP slopes + transpose (unchanged; measured 7.7us).
// ---------------------------------------------------------------------------
__global__ void __launch_bounds__(256) prep_kernel(const float* __restrict__ coeffs) {
    __shared__ float sy[32][KK + 1];
    const int i  = blockIdx.x;
    const int o0 = blockIdx.y * 32;
    const int t  = threadIdx.x;
    const float hk   = 1.0f / 63.0f;
    const float EPSf = 1e-12f;

    #pragma unroll
    for (int j = 0; j < 8; j++) {
        const int lin = t + j * 256;
        const int ol  = lin >> 6;
        const int k   = lin & 63;
        sy[ol][k] = coeffs[((size_t)(o0 + ol) * D_IN + i) * KK + k];
    }
    __syncthreads();

    const int ol = t & 31;
    const int kb = t >> 5;
    const int o  = o0 + ol;

    #pragma unroll
    for (int kk = 0; kk < 8; kk++) {
        const int k = kb * 8 + kk;
        float dk;
        if (k == 0) {
            float d0 = (sy[ol][1] - sy[ol][0]) / (hk + EPSf);
            float d1 = (sy[ol][2] - sy[ol][1]) / (hk + EPSf);
            float di = (3.0f * hk * d0 - hk * d1) / (2.0f * hk + EPSf);
            if (di * d0 <= 0.0f) di = 0.0f;
            if (fabsf(di) > 3.0f * fabsf(d0)) di = 3.0f * d0;
            dk = di;
        } else if (k == 63) {
            float d62 = (sy[ol][63] - sy[ol][62]) / (hk + EPSf);
            float d61 = (sy[ol][62] - sy[ol][61]) / (hk + EPSf);
            float di  = (3.0f * hk * d62 - hk * d61) / (2.0f * hk + EPSf);
            if (di * d62 <= 0.0f) di = 0.0f;
            if (fabsf(di) > 3.0f * fabsf(d62)) di = 3.0f * d62;
            dk = di;
        } else {
            float dm = (sy[ol][k]     - sy[ol][k - 1]) / (hk + EPSf);
            float dp = (sy[ol][k + 1] - sy[ol][k])     / (hk + EPSf);
            dk = 0.0f;
            if (dm * dp > 0.0f) {
                const float w = 3.0f * hk;
                float denom = w / (dm + EPSf) + w / (dp + EPSf);
                dk = (2.0f * w) / (denom + EPSf);
            }
        }
        const size_t off = ((size_t)i * KK + k) * 2 * D_OUT + o;
        g_CD[off]         = sy[ol][k];
        g_CD[off + D_OUT] = dk;
    }
}

// ---------------------------------------------------------------------------
// Eval: block = 4 batch rows, 256 threads = 8 warps = (row, i-half).
// Warp (r, h) accumulates i in [h*64, h*64+64) for row r over all 128 o
// (lane = o-quad, float4). Doubles warps vs R16 (8192 total -> ~55/SM,
// occ ~86%) and halves each warp's serial dependent-load chain.
// Cross-warp combine: one smem float4 add + bias, written by h==0 warps.
// ---------------------------------------------------------------------------
__global__ void __launch_bounds__(256) kan_eval(const float* __restrict__ x,
                                                const float* __restrict__ bias,
                                                float* __restrict__ out, int B) {
    __shared__ int    s_idx[ROWS][D_IN];    //  2KB  0..62 interior, 101 left, 102 right
    __shared__ float4 s_w[ROWS][D_IN];      //  8KB
    __shared__ float4 s_red[ROWS][32];      //  2KB  partial from h==1 warps

    const int t     = threadIdx.x;
    const int lane  = t & 31;
    const int wid   = t >> 5;
    const int row   = wid >> 1;             // 0..3
    const int ihalf = wid & 1;              // 0..1
    const int b0    = blockIdx.x * ROWS;
    const float hk  = 1.0f / 63.0f;

    // Phase 1: weights. Thread t: row t>>6, i-pair (t&63)*2 -> coalesced float2.
    {
        const int prow = t >> 6;
        const int ip   = (t & 63) * 2;
        const float2 xv2 = *reinterpret_cast<const float2*>(
            x + (size_t)(b0 + prow) * D_IN + ip);
        const float xs[2] = {xv2.x, xv2.y};
        #pragma unroll
        for (int q = 0; q < 2; q++) {
            const float xv = xs[q];
            float4 w; int code;
            if (xv < 0.0f)      { code = 101; w = make_float4(0.f, xv,        0.f, 0.f); }
            else if (xv > 1.0f) { code = 102; w = make_float4(0.f, xv - 1.0f, 0.f, 0.f); }
            else {
                int idx = (int)floorf(xv / hk);
                idx = min(max(idx, 0), KK - 2);
                const float tt = (xv - (float)idx * hk) / hk;
                const float t2 = tt * tt, t3 = t2 * tt;
                w.x = 2.0f * t3 - 3.0f * t2 + 1.0f;   // h00
                w.y = hk * (t3 - 2.0f * t2 + tt);      // h*h10
                w.z = -2.0f * t3 + 3.0f * t2;          // h01
                w.w = hk * (t3 - t2);                  // h*h11
                code = idx;
            }
            s_idx[prow][ip + q] = code;
            s_w[prow][ip + q]   = w;
        }
    }
    __syncthreads();

    const float4* cd4 = reinterpret_cast<const float4*>(g_CD);
    float4 acc = make_float4(0.f, 0.f, 0.f, 0.f);
    const int ib = ihalf * 64;

    #pragma unroll 4
    for (int ii = 0; ii < 64; ii++) {
        const int    i    = ib + ii;
        const int    code = s_idx[row][i];   // broadcast LDS
        const float4 w    = s_w[row][i];     // broadcast LDS.128
        const size_t ibase = (size_t)i * (KK * 2 * D_OUT / 4);   // i * 4096 float4
        if (code < 64) {                     // interior (warp-uniform branch)
            const float4* p = cd4 + ibase + code * 64 + lane;
            const float4 y0  = __ldg(p);
            const float4 dd0 = __ldg(p + 32);
            const float4 y1  = __ldg(p + 64);
            const float4 dd1 = __ldg(p + 96);
            acc.x += w.x * y0.x + w.y * dd0.x + w.z * y1.x + w.w * dd1.x;
            acc.y += w.x * y0.y + w.y * dd0.y + w.z * y1.y + w.w * dd1.y;
            acc.z += w.x * y0.z + w.y * dd0.z + w.z * y1.z + w.w * dd1.z;
            acc.w += w.x * y0.w + w.y * dd0.w + w.z * y1.w + w.w * dd1.w;
        } else {                             // extrapolation: 2 hot loads (L1)
            const float4* p = cd4 + ibase + ((code == 101) ? 0 : 63 * 64) + lane;
            const float4 c = __ldg(p);
            const float4 d = __ldg(p + 32);
            acc.x += c.x + w.y * d.x;
            acc.y += c.y + w.y * d.y;
            acc.z += c.z + w.y * d.z;
            acc.w += c.w + w.y * d.w;
        }
    }

    // Combine the two i-halves: h==1 warps publish, h==0 warps finalize.
    if (ihalf == 1) s_red[row][lane] = acc;
    __syncthreads();
    if (ihalf == 0) {
        const float4 o2 = s_red[row][lane];
        const float4 bv = __ldg(reinterpret_cast<const float4*>(bias) + lane);
        acc.x += o2.x + bv.x;
        acc.y += o2.y + bv.y;
        acc.z += o2.z + bv.z;
        acc.w += o2.w + bv.w;
        *reinterpret_cast<float4*>(out + (size_t)(b0 + row) * D_OUT + lane * 4) = acc;
    }
}

// ---------------------------------------------------------------------------
extern "C" void kernel_launch(void* const* d_in, const int* in_sizes, int n_in,
                              void* d_out, int out_size) {
    const float* x      = (const float*)d_in[0];   // [B, 128]
    const float* coeffs = (const float*)d_in[1];   // [128, 128, 64]
    const float* bias   = (const float*)d_in[2];   // [128]
    // d_in[3] = knots: uniform linspace(0,1,64) -> baked-in constants.

    const int B = in_sizes[0] / D_IN;              // 4096

    prep_kernel<<<dim3(D_IN, D_OUT / 32), 256>>>(coeffs);
    kan_eval<<<B / ROWS, 256>>>(x, bias, (float*)d_out, B);
}